// round 3
// baseline (speedup 1.0000x reference)
#include <cuda_runtime.h>
#include <cstdint>

#define T_FRAMES 60
#define HID 32
#define NG 128          // 4*HID gate rows
#define EPSF 1e-5f
#define L2E 1.4426950408889634f
#define FULLM 0xffffffffu

// scratch: per-frame input-side gate pre-activations (biases included, log2-scaled)
__device__ float g_gx[T_FRAMES * NG];
__device__ int   g_done = 0;

// ---- packed f32x2 helpers (Blackwell) -------------------------------------
__device__ __forceinline__ unsigned long long pack2(float lo, float hi) {
    unsigned long long r;
    asm("mov.b64 %0, {%1, %2};" : "=l"(r) : "f"(lo), "f"(hi));
    return r;
}
__device__ __forceinline__ void unpack2(unsigned long long v, float& lo, float& hi) {
    asm("mov.b64 {%0, %1}, %2;" : "=f"(lo), "=f"(hi) : "l"(v));
}
__device__ __forceinline__ unsigned long long ffma2(unsigned long long a,
                                                    unsigned long long b,
                                                    unsigned long long c) {
    unsigned long long d;
    asm("fma.rn.f32x2 %0, %1, %2, %3;" : "=l"(d) : "l"(a), "l"(b), "l"(c));
    return d;
}
__device__ __forceinline__ unsigned long long add2(unsigned long long a,
                                                   unsigned long long b) {
    unsigned long long d;
    asm("add.rn.f32x2 %0, %1, %2;" : "=l"(d) : "l"(a), "l"(b));
    return d;
}
__device__ __forceinline__ float ex2a(float x) {
    float r; asm("ex2.approx.f32 %0, %1;" : "=f"(r) : "f"(x)); return r;
}
__device__ __forceinline__ float rcpa(float x) {
    float r; asm("rcp.approx.f32 %0, %1;" : "=f"(r) : "f"(x)); return r;
}
// sigmoid with input already scaled by log2(e): 1/(1+2^-x)
__device__ __forceinline__ float sigm_s(float xs) {
    return rcpa(1.0f + ex2a(-xs));
}
// tanh with input already scaled by 2*log2(e): 2/(1+2^-x) - 1
__device__ __forceinline__ float tanh_s(float xs) {
    return fmaf(2.0f, rcpa(1.0f + ex2a(-xs)), -1.0f);
}

// ---------------------------------------------------------------------------
// Fused persistent kernel: blocks 0..59 do the per-frame MLP+LN+W_ih matvec
// (fully parallel), block 60 runs the recurrence + output head, synchronized
// via threadfence + atomic counter. Single wave (61 blocks << 148 SMs).
// ---------------------------------------------------------------------------
__global__ void __launch_bounds__(128, 1) fused_kernel(
    const float* __restrict__ x,
    const float* __restrict__ w00, const float* __restrict__ b00,
    const float* __restrict__ w01, const float* __restrict__ b01,
    const float* __restrict__ lng, const float* __restrict__ lnb,
    const float* __restrict__ wih, const float* __restrict__ bih,
    const float* __restrict__ bhh,
    const float* __restrict__ whh,
    const float* __restrict__ bng, const float* __restrict__ bnb,
    const float* __restrict__ w10, const float* __restrict__ b10,
    const float* __restrict__ w11, const float* __restrict__ b11,
    const float* __restrict__ w12, const float* __restrict__ b12,
    float* __restrict__ out)
{
    const int tid = threadIdx.x;

    if (blockIdx.x < T_FRAMES) {
        // =================== frame path (parallel over t) ===================
        const int t = blockIdx.x;

        __shared__ float sx[63];
        __shared__ float sf1[63];
        __shared__ float sf2[64];
        __shared__ float sfn[64];
        __shared__ float s_mu, s_rstd;

        if (tid < 63) sx[tid] = x[t * 63 + tid];
        __syncthreads();

        if (tid < 63) {
            float acc = b00[tid];
            const float* wr = w00 + tid * 63;
            #pragma unroll
            for (int k = 0; k < 63; k++) acc = fmaf(wr[k], sx[k], acc);
            sf1[tid] = fmaxf(acc, 0.0f);
        }
        __syncthreads();

        if (tid < 64) {
            float acc = b01[tid];
            const float* wr = w01 + tid * 63;
            #pragma unroll
            for (int k = 0; k < 63; k++) acc = fmaf(wr[k], sf1[k], acc);
            sf2[tid] = fmaxf(acc, 0.0f);
        }
        __syncthreads();

        if (tid < 32) {
            float v0 = sf2[tid], v1 = sf2[tid + 32];
            float s = v0 + v1;
            float q = v0 * v0 + v1 * v1;
            #pragma unroll
            for (int o = 16; o > 0; o >>= 1) {
                s += __shfl_xor_sync(FULLM, s, o);
                q += __shfl_xor_sync(FULLM, q, o);
            }
            if (tid == 0) {
                float mu  = s * (1.0f / 64.0f);
                float var = q * (1.0f / 64.0f) - mu * mu;
                s_mu   = mu;
                s_rstd = rsqrtf(var + EPSF);
            }
        }
        __syncthreads();

        if (tid < 64)
            sfn[tid] = (sf2[tid] - s_mu) * s_rstd * lng[tid] + lnb[tid];
        __syncthreads();

        // gate pre-activation row per thread, pre-scaled into log2 domain:
        // i/f/o rows -> *log2(e); g rows (64..95) -> *2*log2(e)
        {
            float acc = bih[tid] + bhh[tid];
            const float* wr = wih + tid * 64;
            #pragma unroll
            for (int k = 0; k < 64; k++) acc = fmaf(wr[k], sfn[k], acc);
            float scale = ((tid >> 5) == 2) ? (2.0f * L2E) : L2E;
            g_gx[t * NG + tid] = acc * scale;
        }
        __syncthreads();
        if (tid == 0) {
            __threadfence();
            atomicAdd(&g_done, 1);
        }
        return;
    }

    // ======================= sequential path (block 60) =====================
    if (tid >= 32) return;
    const int lane = tid;

    // Load + pack W_hh into registers (overlaps with frame blocks running).
    // wif[k] = (wi[k]*L2E, wf[k]*L2E); wgo[k] = (wg[k]*2*L2E, wo[k]*L2E)
    unsigned long long wif[HID], wgo[HID];
    {
        const float* ri = whh + (lane      ) * HID;
        const float* rf = whh + (lane + 32 ) * HID;
        const float* rg = whh + (lane + 64 ) * HID;
        const float* ro = whh + (lane + 96 ) * HID;
        #pragma unroll
        for (int k = 0; k < HID; k++) {
            wif[k] = pack2(ri[k] * L2E, rf[k] * L2E);
            wgo[k] = pack2(rg[k] * (2.0f * L2E), ro[k] * L2E);
        }
    }

    // Wait for all frame blocks.
    if (lane == 0) {
        volatile int* p = &g_done;
        while (*p < T_FRAMES) { }
    }
    __syncwarp();
    __threadfence();

    // ---- t = 0 peeled: h = 0, so gates are just gx[0] ----
    float gi = g_gx[lane];
    float gf = g_gx[lane + 32];
    float gg = g_gx[lane + 64];
    float go = g_gx[lane + 96];

    float c = sigm_s(gf) * 0.0f + sigm_s(gi) * tanh_s(gg);
    float h = sigm_s(go) * tanh_s(c * (2.0f * L2E));
    unsigned long long hh = pack2(h, h);

    // prefetch gx[1]
    float pi = g_gx[NG + lane];
    float pf = g_gx[NG + lane + 32];
    float pg = g_gx[NG + lane + 64];
    float po = g_gx[NG + lane + 96];

    #pragma unroll 2
    for (int t = 1; t < T_FRAMES; t++) {
        unsigned long long aif0 = pack2(pi, pf), ago0 = pack2(pg, po);
        unsigned long long aif1 = 0ull,          ago1 = 0ull;

        if (t + 1 < T_FRAMES) {          // prefetch next frame's gates
            const float* g = g_gx + (t + 1) * NG;
            pi = g[lane]; pf = g[lane + 32]; pg = g[lane + 64]; po = g[lane + 96];
        }

        #pragma unroll
        for (int k = 0; k < HID; k += 2) {
            unsigned long long h0 = __shfl_sync(FULLM, hh, k);
            unsigned long long h1 = __shfl_sync(FULLM, hh, k + 1);
            aif0 = ffma2(wif[k],     h0, aif0);
            ago0 = ffma2(wgo[k],     h0, ago0);
            aif1 = ffma2(wif[k + 1], h1, aif1);
            ago1 = ffma2(wgo[k + 1], h1, ago1);
        }
        unpack2(add2(aif0, aif1), gi, gf);
        unpack2(add2(ago0, ago1), gg, go);

        float si = sigm_s(gi);
        float sf = sigm_s(gf);
        float tg = tanh_s(gg);
        float so = sigm_s(go);
        c = fmaf(sf, c, si * tg);
        h = so * tanh_s(c * (2.0f * L2E));
        hh = pack2(h, h);
    }

    // ---- output head (warp 0, shuffles only) ----
    float hb = (h * rsqrtf(1.0f + EPSF)) * bng[lane] + bnb[lane];

    float o1 = b10[lane];
    #pragma unroll
    for (int k = 0; k < 32; k++)
        o1 = fmaf(w10[lane * 32 + k], __shfl_sync(FULLM, hb, k), o1);
    o1 = fmaxf(o1, 0.0f);

    float o2 = b11[lane];
    #pragma unroll
    for (int k = 0; k < 32; k++)
        o2 = fmaf(w11[lane * 32 + k], __shfl_sync(FULLM, o1, k), o2);
    o2 = fmaxf(o2, 0.0f);

    float acc[8];
    #pragma unroll
    for (int m = 0; m < 8; m++) acc[m] = b12[m * 32 + lane];
    #pragma unroll
    for (int k = 0; k < 32; k++) {
        float v = __shfl_sync(FULLM, o2, k);
        #pragma unroll
        for (int m = 0; m < 8; m++)
            acc[m] = fmaf(w12[(m * 32 + lane) * 32 + k], v, acc[m]);
    }
    #pragma unroll
    for (int m = 0; m < 8; m++) out[m * 32 + lane] = acc[m];

    // reset the counter for the next graph replay (all producers finished,
    // all consumption done; next launch cannot start before this kernel ends)
    if (lane == 0) g_done = 0;
}

// ---------------------------------------------------------------------------
// Input order (metadata): x, w00, b00, w01, b01, ln_g, ln_b, w_ih, w_hh,
//                         b_ih, b_hh, bn_g, bn_b, w10, b10, w11, b11, w12, b12
// ---------------------------------------------------------------------------
extern "C" void kernel_launch(void* const* d_in, const int* in_sizes, int n_in,
                              void* d_out, int out_size)
{
    const float* x    = (const float*)d_in[0];
    const float* w00  = (const float*)d_in[1];
    const float* b00  = (const float*)d_in[2];
    const float* w01  = (const float*)d_in[3];
    const float* b01  = (const float*)d_in[4];
    const float* lng  = (const float*)d_in[5];
    const float* lnb  = (const float*)d_in[6];
    const float* wih  = (const float*)d_in[7];
    const float* whh  = (const float*)d_in[8];
    const float* bih  = (const float*)d_in[9];
    const float* bhh  = (const float*)d_in[10];
    const float* bng  = (const float*)d_in[11];
    const float* bnb  = (const float*)d_in[12];
    const float* w10  = (const float*)d_in[13];
    const float* b10  = (const float*)d_in[14];
    const float* w11  = (const float*)d_in[15];
    const float* b11  = (const float*)d_in[16];
    const float* w12  = (const float*)d_in[17];
    const float* b12  = (const float*)d_in[18];
    float* out = (float*)d_out;

    fused_kernel<<<T_FRAMES + 1, 128>>>(
        x, w00, b00, w01, b01, lng, lnb, wih, bih, bhh,
        whh, bng, bnb, w10, b10, w11, b11, w12, b12, out);
}

// round 4
// speedup vs baseline: 1.2728x; 1.2728x over previous
#include <cuda_runtime.h>

#define T_FRAMES 60
#define HID 32
#define NG 128          // 4*HID gate rows
#define EPSF 1e-5f
#define FULLM 0xffffffffu

// scratch: per-frame input-side gate pre-activations.
// i/f/o rows pre-scaled by 0.5 (sigmoid-via-tanh); g rows unscaled.
__device__ float g_gx[T_FRAMES * NG];

__device__ __forceinline__ float tanha(float x) {
    float r; asm("tanh.approx.f32 %0, %1;" : "=f"(r) : "f"(x)); return r;
}

// ---------------------------------------------------------------------------
// Kernel 1: one block per frame (fully parallel across t).
//   f1 = relu(W00 x_t + b00); f2 = relu(W01 f1 + b01)
//   fn = LayerNorm(f2)*ln_g + ln_b
//   gx = W_ih fn + b_ih + b_hh   (i/f/o rows scaled by 0.5)
// ---------------------------------------------------------------------------
__global__ void frame_kernel(const float* __restrict__ x,
                             const float* __restrict__ w00, const float* __restrict__ b00,
                             const float* __restrict__ w01, const float* __restrict__ b01,
                             const float* __restrict__ lng, const float* __restrict__ lnb,
                             const float* __restrict__ wih, const float* __restrict__ bih,
                             const float* __restrict__ bhh)
{
    const int t = blockIdx.x;
    const int tid = threadIdx.x;

    __shared__ float sx[63];
    __shared__ float sf1[63];
    __shared__ float sf2[64];
    __shared__ float sfn[64];
    __shared__ float s_mu, s_rstd;

    if (tid < 63) sx[tid] = x[t * 63 + tid];
    __syncthreads();

    if (tid < 63) {
        float acc = b00[tid];
        const float* wr = w00 + tid * 63;
        #pragma unroll
        for (int k = 0; k < 63; k++) acc = fmaf(wr[k], sx[k], acc);
        sf1[tid] = fmaxf(acc, 0.0f);
    }
    __syncthreads();

    if (tid < 64) {
        float acc = b01[tid];
        const float* wr = w01 + tid * 63;
        #pragma unroll
        for (int k = 0; k < 63; k++) acc = fmaf(wr[k], sf1[k], acc);
        sf2[tid] = fmaxf(acc, 0.0f);
    }
    __syncthreads();

    if (tid < 32) {
        float v0 = sf2[tid], v1 = sf2[tid + 32];
        float s = v0 + v1;
        float q = v0 * v0 + v1 * v1;
        #pragma unroll
        for (int o = 16; o > 0; o >>= 1) {
            s += __shfl_xor_sync(FULLM, s, o);
            q += __shfl_xor_sync(FULLM, q, o);
        }
        if (tid == 0) {
            float mu  = s * (1.0f / 64.0f);
            float var = q * (1.0f / 64.0f) - mu * mu;
            s_mu   = mu;
            s_rstd = rsqrtf(var + EPSF);
        }
    }
    __syncthreads();

    if (tid < 64)
        sfn[tid] = (sf2[tid] - s_mu) * s_rstd * lng[tid] + lnb[tid];
    __syncthreads();

    {
        float acc = bih[tid] + bhh[tid];
        const float* wr = wih + tid * 64;
        #pragma unroll
        for (int k = 0; k < 64; k++) acc = fmaf(wr[k], sfn[k], acc);
        // g gate rows (64..95) unscaled; i/f/o rows scaled by 0.5
        float scale = ((tid >> 5) == 2) ? 1.0f : 0.5f;
        g_gx[t * NG + tid] = acc * scale;
    }
}

// ---------------------------------------------------------------------------
// Kernel 2: single block; warp 0 runs the recurrence with register-resident
// W_hh (4 rows/lane), register h/c, 32-bit shuffles, smem gx.
// Activations via HW tanh.approx (sigmoid = 0.5*tanh(0.5x)+0.5, the 0.5
// pre-folded into weights/gx). Dual accumulators per gate.
// ---------------------------------------------------------------------------
__global__ void __launch_bounds__(128, 1) seq_kernel(
    const float* __restrict__ whh,
    const float* __restrict__ bng, const float* __restrict__ bnb,
    const float* __restrict__ w10, const float* __restrict__ b10,
    const float* __restrict__ w11, const float* __restrict__ b11,
    const float* __restrict__ w12, const float* __restrict__ b12,
    float* __restrict__ out)
{
    __shared__ float sgx[T_FRAMES * NG];       // 30 KB
    const int tid = threadIdx.x;

    // cooperative preload of gx into smem (vectorized)
    {
        float4* s4 = reinterpret_cast<float4*>(sgx);
        const float4* g4 = reinterpret_cast<const float4*>(g_gx);
        #pragma unroll
        for (int i = tid; i < (T_FRAMES * NG) / 4; i += 128) s4[i] = g4[i];
    }
    __syncthreads();
    if (tid >= 32) return;     // warps 1..3 were only for the preload

    const int lane = tid;

    // W_hh rows (lane), (+32), (+64), (+96) -> registers.
    // i/f/o rows pre-scaled by 0.5 (sigmoid-via-tanh); g rows unscaled.
    float wi[HID], wf[HID], wg[HID], wo[HID];
    {
        const float* ri = whh + (lane      ) * HID;
        const float* rf = whh + (lane + 32 ) * HID;
        const float* rg = whh + (lane + 64 ) * HID;
        const float* ro = whh + (lane + 96 ) * HID;
        #pragma unroll
        for (int k = 0; k < HID; k++) {
            wi[k] = ri[k] * 0.5f;
            wf[k] = rf[k] * 0.5f;
            wg[k] = rg[k];
            wo[k] = ro[k] * 0.5f;
        }
    }

    // ---- t = 0 peeled: h = 0 -> gates are just gx[0] ----
    float gi = sgx[lane];
    float gf = sgx[lane + 32];
    float gg = sgx[lane + 64];
    float go = sgx[lane + 96];

    float si = fmaf(0.5f, tanha(gi), 0.5f);
    float so = fmaf(0.5f, tanha(go), 0.5f);
    float c  = si * tanha(gg);              // f-gate term vanishes (c0 = 0)
    float h  = so * tanha(c);
    (void)gf;

    #pragma unroll 1
    for (int t = 1; t < T_FRAMES; t++) {
        const float* gp = sgx + t * NG;
        float gi0 = gp[lane],      gi1 = 0.0f;
        float gf0 = gp[lane + 32], gf1 = 0.0f;
        float gg0 = gp[lane + 64], gg1 = 0.0f;
        float go0 = gp[lane + 96], go1 = 0.0f;

        #pragma unroll
        for (int k = 0; k < HID; k += 2) {
            float h0 = __shfl_sync(FULLM, h, k);
            float h1 = __shfl_sync(FULLM, h, k + 1);
            gi0 = fmaf(wi[k], h0, gi0);  gi1 = fmaf(wi[k + 1], h1, gi1);
            gf0 = fmaf(wf[k], h0, gf0);  gf1 = fmaf(wf[k + 1], h1, gf1);
            gg0 = fmaf(wg[k], h0, gg0);  gg1 = fmaf(wg[k + 1], h1, gg1);
            go0 = fmaf(wo[k], h0, go0);  go1 = fmaf(wo[k + 1], h1, go1);
        }

        float ti = tanha(gi0 + gi1);
        float tf = tanha(gf0 + gf1);
        float tg = tanha(gg0 + gg1);
        float to = tanha(go0 + go1);
        float si2 = fmaf(0.5f, ti, 0.5f);
        float sf2 = fmaf(0.5f, tf, 0.5f);
        float so2 = fmaf(0.5f, to, 0.5f);
        c = fmaf(sf2, c, si2 * tg);
        h = so2 * tanha(c);
    }

    // ---- output head (warp 0, shuffles only) ----
    // BatchNorm1d eval with running_mean=0, running_var=1:
    float hb = (h * rsqrtf(1.0f + EPSF)) * bng[lane] + bnb[lane];

    float o1 = b10[lane];
    #pragma unroll
    for (int k = 0; k < 32; k++)
        o1 = fmaf(w10[lane * 32 + k], __shfl_sync(FULLM, hb, k), o1);
    o1 = fmaxf(o1, 0.0f);

    float o2 = b11[lane];
    #pragma unroll
    for (int k = 0; k < 32; k++)
        o2 = fmaf(w11[lane * 32 + k], __shfl_sync(FULLM, o1, k), o2);
    o2 = fmaxf(o2, 0.0f);

    float acc[8];
    #pragma unroll
    for (int m = 0; m < 8; m++) acc[m] = b12[m * 32 + lane];
    #pragma unroll
    for (int k = 0; k < 32; k++) {
        float v = __shfl_sync(FULLM, o2, k);
        #pragma unroll
        for (int m = 0; m < 8; m++)
            acc[m] = fmaf(w12[(m * 32 + lane) * 32 + k], v, acc[m]);
    }
    #pragma unroll
    for (int m = 0; m < 8; m++) out[m * 32 + lane] = acc[m];
}

// ---------------------------------------------------------------------------
// Input order (metadata): x, w00, b00, w01, b01, ln_g, ln_b, w_ih, w_hh,
//                         b_ih, b_hh, bn_g, bn_b, w10, b10, w11, b11, w12, b12
// ---------------------------------------------------------------------------
extern "C" void kernel_launch(void* const* d_in, const int* in_sizes, int n_in,
                              void* d_out, int out_size)
{
    const float* x    = (const float*)d_in[0];
    const float* w00  = (const float*)d_in[1];
    const float* b00  = (const float*)d_in[2];
    const float* w01  = (const float*)d_in[3];
    const float* b01  = (const float*)d_in[4];
    const float* lng  = (const float*)d_in[5];
    const float* lnb  = (const float*)d_in[6];
    const float* wih  = (const float*)d_in[7];
    const float* whh  = (const float*)d_in[8];
    const float* bih  = (const float*)d_in[9];
    const float* bhh  = (const float*)d_in[10];
    const float* bng  = (const float*)d_in[11];
    const float* bnb  = (const float*)d_in[12];
    const float* w10  = (const float*)d_in[13];
    const float* b10  = (const float*)d_in[14];
    const float* w11  = (const float*)d_in[15];
    const float* b11  = (const float*)d_in[16];
    const float* w12  = (const float*)d_in[17];
    const float* b12  = (const float*)d_in[18];
    float* out = (float*)d_out;

    frame_kernel<<<T_FRAMES, 128>>>(x, w00, b00, w01, b01, lng, lnb, wih, bih, bhh);
    seq_kernel<<<1, 128>>>(whh, bng, bnb, w10, b10, w11, b11, w12, b12, out);
}